// round 1
// baseline (speedup 1.0000x reference)
#include <cuda_runtime.h>
#include <math.h>

#define Bc 2048
#define Dc 24
#define Hc 256
#define Lc 64
#define Vc 780
#define Tc 23               /* D-1 steps per scan direction */
#define Sc 47               /* 2D-1 p-rows per tree */
#define DB (Dc*Bc)          /* 49152 */
#define TB (Tc*Bc)          /* 47104 */
#define SB (Sc*Bc)          /* 96256 */
#define QBLOCKS (DB/8)      /* 6144 */
#define PBLOCKS (SB/8)      /* 12032 */

// ---------------- scratch (static device allocations; no runtime alloc) ----
__device__ float g_Az[DB*Hc];      // x @ Wz[:, :H]^T + bz   [D][B][H]
__device__ float g_Ah[DB*Hc];      // x @ Wh[:, :H]^T + bh
__device__ float g_Ar[DB*Hc];      // x @ Wr^T + br
__device__ float g_Px[DB*Hc];      // x @ U_w[:, :H]^T
__device__ float g_mf[TB*Hc];      // forward messages m_f[t][B][H]
__device__ float g_mr[TB*Hc];      // reverse messages m_r[t][B][H]
__device__ float g_rmf[Bc*Hc];     // r*m carry, forward dir
__device__ float g_rmr[Bc*Hc];     // r*m carry, reverse dir
__device__ float g_Pq [TB*Hc];     // m_f @ W_w[:, :H]^T
__device__ float g_Pmf[TB*Hc];     // m_f @ U_w[:, H:2H]^T
__device__ float g_Pmr[TB*Hc];     // m_r @ U_w[:, H:2H]^T
__device__ float g_Tq[Bc*Hc];      // tree_vec @ W_w[:, H:H+L]^T + W_b
__device__ float g_Tp[Bc*Hc];      // tree_vec @ U_w[:, 2H:2H+L]^T + U_b
__device__ float g_logits[(size_t)DB*Vc];
__device__ float g_qpart_loss[QBLOCKS];
__device__ float g_qpart_corr[QBLOCKS];
__device__ float g_ppart_loss[PBLOCKS];
__device__ float g_ppart_corr[PBLOCKS];

__device__ __forceinline__ float sigf(float x) { return 1.f / (1.f + expf(-x)); }

// ------------- shared 64x64 fp32 GEMM tile core, K=256 ---------------------
// arow/brow: per-thread row pointers (already offset to this thread's load
// row, contiguous along k). nullptr -> zeros. acc[i][j]: rows ty*4+i, cols tx*4+j.
__device__ __forceinline__ void gemm_k256(
    const float* __restrict__ arow, const float* __restrict__ brow,
    float (*As)[64], float (*Bs)[64],
    int lr, int lk, int tx, int ty, float acc[4][4])
{
    for (int k0 = 0; k0 < Hc; k0 += 16) {
        float4 av = make_float4(0.f, 0.f, 0.f, 0.f);
        float4 bv = make_float4(0.f, 0.f, 0.f, 0.f);
        if (arow) av = *(const float4*)(arow + k0 + lk);
        if (brow) bv = *(const float4*)(brow + k0 + lk);
        As[lk + 0][lr] = av.x; As[lk + 1][lr] = av.y;
        As[lk + 2][lr] = av.z; As[lk + 3][lr] = av.w;
        Bs[lk + 0][lr] = bv.x; Bs[lk + 1][lr] = bv.y;
        Bs[lk + 2][lr] = bv.z; Bs[lk + 3][lr] = bv.w;
        __syncthreads();
#pragma unroll
        for (int k = 0; k < 16; k++) {
            float4 a = *(const float4*)(&As[k][ty * 4]);
            float4 b = *(const float4*)(&Bs[k][tx * 4]);
            acc[0][0] += a.x * b.x; acc[0][1] += a.x * b.y; acc[0][2] += a.x * b.z; acc[0][3] += a.x * b.w;
            acc[1][0] += a.y * b.x; acc[1][1] += a.y * b.y; acc[1][2] += a.y * b.z; acc[1][3] += a.y * b.w;
            acc[2][0] += a.z * b.x; acc[2][1] += a.z * b.y; acc[2][2] += a.z * b.z; acc[2][3] += a.z * b.w;
            acc[3][0] += a.w * b.x; acc[3][1] += a.w * b.y; acc[3][2] += a.w * b.z; acc[3][3] += a.w * b.w;
        }
        __syncthreads();
    }
}

// ------------- precompute x-side products (gathered emb rows) --------------
// z=0: Wz[:, :H]+bz -> g_Az   z=1: Wh[:, :H]+bh -> g_Ah
// z=2: Wr+br        -> g_Ar   z=3: U_w[:, :H]   -> g_Px
__global__ void k_precompute_x(
    const int* __restrict__ wid, const float* __restrict__ emb,
    const float* __restrict__ Wz, const float* __restrict__ bz,
    const float* __restrict__ Wh, const float* __restrict__ bh,
    const float* __restrict__ Wr, const float* __restrict__ br,
    const float* __restrict__ U_w)
{
    __shared__ __align__(16) float As[16][64];
    __shared__ __align__(16) float Bs[16][64];
    int tid = threadIdx.x, tx = tid & 15, ty = tid >> 4;
    int lr = tid >> 2, lk = (tid & 3) << 2;
    int rowBase = blockIdx.x * 64, colBase = blockIdx.y * 64;
    int z = blockIdx.z;

    const float* W; int ld; const float* bias; float* out;
    if      (z == 0) { W = Wz;  ld = 2*Hc;      bias = bz; out = g_Az; }
    else if (z == 1) { W = Wh;  ld = 2*Hc;      bias = bh; out = g_Ah; }
    else if (z == 2) { W = Wr;  ld = Hc;        bias = br; out = g_Ar; }
    else             { W = U_w; ld = 2*Hc + Lc; bias = 0;  out = g_Px; }

    int r = rowBase + lr;
    int d = r >> 11, b = r & (Bc - 1);
    const float* arow = emb + (size_t)wid[b * Dc + d] * Hc;
    const float* brow = W + (size_t)(colBase + lr) * ld;

    float acc[4][4] = {};
    gemm_k256(arow, brow, As, Bs, lr, lk, tx, ty, acc);

#pragma unroll
    for (int i = 0; i < 4; i++) {
        int rr = rowBase + ty * 4 + i;
        int cc = colBase + tx * 4;
        float4 o;
        float b0 = bias ? bias[cc + 0] : 0.f, b1 = bias ? bias[cc + 1] : 0.f;
        float b2 = bias ? bias[cc + 2] : 0.f, b3 = bias ? bias[cc + 3] : 0.f;
        o.x = acc[i][0] + b0; o.y = acc[i][1] + b1;
        o.z = acc[i][2] + b2; o.w = acc[i][3] + b3;
        *(float4*)(out + (size_t)rr * Hc + cc) = o;
    }
}

// ------------- tree_vec small GEMMs ----------------------------------------
__global__ void k_tree(const float* __restrict__ tv,
                       const float* __restrict__ W_w, const float* __restrict__ W_b,
                       const float* __restrict__ U_w, const float* __restrict__ U_b)
{
    int b = blockIdx.x, z = blockIdx.y, n = threadIdx.x;
    __shared__ float s_tv[Lc];
    if (n < Lc) s_tv[n] = tv[(size_t)b * Lc + n];
    __syncthreads();
    const float* W; int ld, koff; const float* bias; float* out;
    if (z == 0) { W = W_w; ld = Hc + Lc;     koff = Hc;     bias = W_b; out = g_Tq; }
    else        { W = U_w; ld = 2*Hc + Lc;   koff = 2*Hc;   bias = U_b; out = g_Tp; }
    const float* wr = W + (size_t)n * ld + koff;
    float s = bias[n];
#pragma unroll
    for (int k = 0; k < Lc; k += 4) {
        float4 w4 = *(const float4*)(wr + k);
        s += s_tv[k]*w4.x + s_tv[k+1]*w4.y + s_tv[k+2]*w4.z + s_tv[k+3]*w4.w;
    }
    out[(size_t)b * Hc + n] = s;
}

// ------------- scan phase A: z/mt GEMMs + GRU update -----------------------
__global__ void k_scanA(int t, const float* __restrict__ Wz, const float* __restrict__ Wh)
{
    __shared__ __align__(16) float As[16][64];
    __shared__ __align__(16) float Bs[16][64];
    int tid = threadIdx.x, tx = tid & 15, ty = tid >> 4;
    int lr = tid >> 2, lk = (tid & 3) << 2;
    int rowBase = blockIdx.x * 64, colBase = blockIdx.y * 64;
    int dir = rowBase >= Bc;
    int rb = rowBase - (dir ? Bc : 0);
    int srcd = dir ? (Tc - t) : t;

    const float* Az = g_Az + ((size_t)srcd * Bc + rb) * Hc;
    const float* Ah = g_Ah + ((size_t)srcd * Bc + rb) * Hc;
    const float* mbase = dir ? g_mr : g_mf;
    const float* mprev  = (t > 0) ? mbase + ((size_t)(t-1) * Bc + rb) * Hc : (const float*)0;
    const float* rmprev = (t > 0) ? ((dir ? g_rmr : g_rmf) + (size_t)rb * Hc) : (const float*)0;
    float* mout = (dir ? g_mr : g_mf) + ((size_t)t * Bc + rb) * Hc;

    float accz[4][4] = {}, acch[4][4] = {};
    if (t > 0) {
        const float* uzrow = Wz + (size_t)(colBase + lr) * (2*Hc) + Hc;
        const float* uhrow = Wh + (size_t)(colBase + lr) * (2*Hc) + Hc;
        gemm_k256(mprev  + (size_t)lr * Hc, uzrow, As, Bs, lr, lk, tx, ty, accz);
        gemm_k256(rmprev + (size_t)lr * Hc, uhrow, As, Bs, lr, lk, tx, ty, acch);
    }

#pragma unroll
    for (int i = 0; i < 4; i++) {
        int q = ty * 4 + i;
        int c = colBase + tx * 4;
        float4 az4 = *(const float4*)(Az + (size_t)q * Hc + c);
        float4 ah4 = *(const float4*)(Ah + (size_t)q * Hc + c);
        float4 mp4 = (t > 0) ? *(const float4*)(mprev + (size_t)q * Hc + c)
                             : make_float4(0.f, 0.f, 0.f, 0.f);
        float4 o;
        {
            float zz = sigf(accz[i][0] + az4.x), mt = tanhf(acch[i][0] + ah4.x);
            o.x = (1.f - zz) * mp4.x + zz * mt;
        }
        {
            float zz = sigf(accz[i][1] + az4.y), mt = tanhf(acch[i][1] + ah4.y);
            o.y = (1.f - zz) * mp4.y + zz * mt;
        }
        {
            float zz = sigf(accz[i][2] + az4.z), mt = tanhf(acch[i][2] + ah4.z);
            o.z = (1.f - zz) * mp4.z + zz * mt;
        }
        {
            float zz = sigf(accz[i][3] + az4.w), mt = tanhf(acch[i][3] + ah4.w);
            o.w = (1.f - zz) * mp4.w + zz * mt;
        }
        *(float4*)(mout + (size_t)q * Hc + c) = o;
    }
}

// ------------- scan phase B: r GEMM + r*m carry ----------------------------
__global__ void k_scanB(int t, const float* __restrict__ Ur)
{
    __shared__ __align__(16) float As[16][64];
    __shared__ __align__(16) float Bs[16][64];
    int tid = threadIdx.x, tx = tid & 15, ty = tid >> 4;
    int lr = tid >> 2, lk = (tid & 3) << 2;
    int rowBase = blockIdx.x * 64, colBase = blockIdx.y * 64;
    int dir = rowBase >= Bc;
    int rb = rowBase - (dir ? Bc : 0);
    int dstd = dir ? (Tc - 1 - t) : (t + 1);

    const float* Ar = g_Ar + ((size_t)dstd * Bc + rb) * Hc;
    const float* mcur = (dir ? g_mr : g_mf) + ((size_t)t * Bc + rb) * Hc;
    float* rmout = (dir ? g_rmr : g_rmf) + (size_t)rb * Hc;

    float acc[4][4] = {};
    gemm_k256(mcur + (size_t)lr * Hc, Ur + (size_t)(colBase + lr) * Hc,
              As, Bs, lr, lk, tx, ty, acc);

#pragma unroll
    for (int i = 0; i < 4; i++) {
        int q = ty * 4 + i;
        int c = colBase + tx * 4;
        float4 ar4 = *(const float4*)(Ar + (size_t)q * Hc + c);
        float4 m4  = *(const float4*)(mcur + (size_t)q * Hc + c);
        float4 o;
        o.x = sigf(acc[i][0] + ar4.x) * m4.x;
        o.y = sigf(acc[i][1] + ar4.y) * m4.y;
        o.z = sigf(acc[i][2] + ar4.z) * m4.z;
        o.w = sigf(acc[i][3] + ar4.w) * m4.w;
        *(float4*)(rmout + (size_t)q * Hc + c) = o;
    }
}

// ------------- message-side products ---------------------------------------
// z=0: m_f @ W_w[:, :H]^T -> g_Pq   z=1: m_f @ U_w[:, H:2H]^T -> g_Pmf
// z=2: m_r @ U_w[:, H:2H]^T -> g_Pmr
__global__ void k_postm(const float* __restrict__ W_w, const float* __restrict__ U_w)
{
    __shared__ __align__(16) float As[16][64];
    __shared__ __align__(16) float Bs[16][64];
    int tid = threadIdx.x, tx = tid & 15, ty = tid >> 4;
    int lr = tid >> 2, lk = (tid & 3) << 2;
    int rowBase = blockIdx.x * 64, colBase = blockIdx.y * 64;
    int z = blockIdx.z;

    const float* A; const float* W; int ld, koff; float* out;
    if      (z == 0) { A = g_mf; W = W_w; ld = Hc + Lc;   koff = 0;  out = g_Pq;  }
    else if (z == 1) { A = g_mf; W = U_w; ld = 2*Hc + Lc; koff = Hc; out = g_Pmf; }
    else             { A = g_mr; W = U_w; ld = 2*Hc + Lc; koff = Hc; out = g_Pmr; }

    const float* arow = A + (size_t)(rowBase + lr) * Hc;
    const float* brow = W + (size_t)(colBase + lr) * ld + koff;
    float acc[4][4] = {};
    gemm_k256(arow, brow, As, Bs, lr, lk, tx, ty, acc);

#pragma unroll
    for (int i = 0; i < 4; i++) {
        int rr = rowBase + ty * 4 + i;
        int cc = colBase + tx * 4;
        float4 o = make_float4(acc[i][0], acc[i][1], acc[i][2], acc[i][3]);
        *(float4*)(out + (size_t)rr * Hc + cc) = o;
    }
}

// ------------- q logits GEMM with fused q1 assembly ------------------------
__global__ void k_logits(const float* __restrict__ Wo, const float* __restrict__ Wob)
{
    __shared__ __align__(16) float As[16][64];
    __shared__ __align__(16) float Bs[16][64];
    int tid = threadIdx.x, tx = tid & 15, ty = tid >> 4;
    int lr = tid >> 2, lk = (tid & 3) << 2;
    int rowBase = blockIdx.x * 64, colBase = blockIdx.y * 64;

    int r = rowBase + lr;
    int d = r >> 11, b = r & (Bc - 1);
    const float* pq = d ? (g_Pq + ((size_t)(d - 1) * Bc + b) * Hc) : (const float*)0;
    const float* tq = g_Tq + (size_t)b * Hc;
    int wrow = colBase + lr;
    const float* brow = (wrow < Vc) ? (Wo + (size_t)wrow * Hc) : (const float*)0;

    float acc[4][4] = {};
    for (int k0 = 0; k0 < Hc; k0 += 16) {
        float4 av = *(const float4*)(tq + k0 + lk);
        if (pq) {
            float4 p4 = *(const float4*)(pq + k0 + lk);
            av.x += p4.x; av.y += p4.y; av.z += p4.z; av.w += p4.w;
        }
        av.x = fmaxf(av.x, 0.f); av.y = fmaxf(av.y, 0.f);
        av.z = fmaxf(av.z, 0.f); av.w = fmaxf(av.w, 0.f);
        float4 bv = brow ? *(const float4*)(brow + k0 + lk) : make_float4(0.f,0.f,0.f,0.f);
        As[lk + 0][lr] = av.x; As[lk + 1][lr] = av.y;
        As[lk + 2][lr] = av.z; As[lk + 3][lr] = av.w;
        Bs[lk + 0][lr] = bv.x; Bs[lk + 1][lr] = bv.y;
        Bs[lk + 2][lr] = bv.z; Bs[lk + 3][lr] = bv.w;
        __syncthreads();
#pragma unroll
        for (int k = 0; k < 16; k++) {
            float4 a = *(const float4*)(&As[k][ty * 4]);
            float4 bb = *(const float4*)(&Bs[k][tx * 4]);
            acc[0][0] += a.x * bb.x; acc[0][1] += a.x * bb.y; acc[0][2] += a.x * bb.z; acc[0][3] += a.x * bb.w;
            acc[1][0] += a.y * bb.x; acc[1][1] += a.y * bb.y; acc[1][2] += a.y * bb.z; acc[1][3] += a.y * bb.w;
            acc[2][0] += a.z * bb.x; acc[2][1] += a.z * bb.y; acc[2][2] += a.z * bb.z; acc[2][3] += a.z * bb.w;
            acc[3][0] += a.w * bb.x; acc[3][1] += a.w * bb.y; acc[3][2] += a.w * bb.z; acc[3][3] += a.w * bb.w;
        }
        __syncthreads();
    }

#pragma unroll
    for (int i = 0; i < 4; i++) {
        int rr = rowBase + ty * 4 + i;
#pragma unroll
        for (int j = 0; j < 4; j++) {
            int cc = colBase + tx * 4 + j;
            if (cc < Vc)
                g_logits[(size_t)rr * Vc + cc] = acc[i][j] + Wob[cc];
        }
    }
}

// ------------- q-head reduction: logsumexp / argmax / loss -----------------
__global__ void k_qreduce(const int* __restrict__ wid)
{
    int warp = threadIdx.x >> 5, lane = threadIdx.x & 31;
    int row = blockIdx.x * 8 + warp;
    const float* qr = g_logits + (size_t)row * Vc;

    float bv = -3.4e38f; int bi = Vc;
    for (int j = lane; j < Vc; j += 32) {
        float v = qr[j];
        if (v > bv) { bv = v; bi = j; }
    }
#pragma unroll
    for (int o = 16; o; o >>= 1) {
        float ov = __shfl_xor_sync(0xffffffffu, bv, o);
        int   oi = __shfl_xor_sync(0xffffffffu, bi, o);
        if (ov > bv || (ov == bv && oi < bi)) { bv = ov; bi = oi; }
    }
    float se = 0.f;
    for (int j = lane; j < Vc; j += 32) se += expf(qr[j] - bv);
#pragma unroll
    for (int o = 16; o; o >>= 1) se += __shfl_xor_sync(0xffffffffu, se, o);

    __shared__ float sl[8], sc[8];
    if (lane == 0) {
        int d = row >> 11, b = row & (Bc - 1);
        int tgt = wid[b * Dc + d];
        float sel = qr[tgt];
        sl[warp] = (bv + logf(se)) - sel;
        sc[warp] = (bi == tgt) ? 1.f : 0.f;
    }
    __syncthreads();
    if (threadIdx.x == 0) {
        float a = 0.f, c = 0.f;
        for (int w = 0; w < 8; w++) { a += sl[w]; c += sc[w]; }
        g_qpart_loss[blockIdx.x] = a;
        g_qpart_corr[blockIdx.x] = c;
    }
}

// ------------- p-head: assemble + relu + GEMV + BCE ------------------------
__global__ void k_p(const float* __restrict__ usw, const float* __restrict__ usb)
{
    int warp = threadIdx.x >> 5, lane = threadIdx.x & 31;
    int row = blockIdx.x * 8 + warp;
    int s = row >> 11, b = row & (Bc - 1);

    int xd, c1, c2;
    if (s == 0)       { xd = 0;        c1 = -1;                         c2 = -1; }
    else if (s <= Tc) { xd = s;        c1 = s - 1;                      c2 = -1; }
    else { int j = s - (Tc + 1); xd = Tc - 1 - j; c1 = (j <= Tc - 2) ? (Tc - 2 - j) : -1; c2 = j; }

    const float* px = g_Px + ((size_t)xd * Bc + b) * Hc;
    const float* tp = g_Tp + (size_t)b * Hc;
    const float* f1 = (c1 >= 0) ? (g_Pmf + ((size_t)c1 * Bc + b) * Hc) : (const float*)0;
    const float* f2 = (c2 >= 0) ? (g_Pmr + ((size_t)c2 * Bc + b) * Hc) : (const float*)0;

    float acc = 0.f;
#pragma unroll
    for (int i = 0; i < 2; i++) {
        int n = (lane + 32 * i) * 4;
        float4 v = *(const float4*)(px + n);
        float4 t4 = *(const float4*)(tp + n);
        v.x += t4.x; v.y += t4.y; v.z += t4.z; v.w += t4.w;
        if (f1) { float4 a4 = *(const float4*)(f1 + n); v.x += a4.x; v.y += a4.y; v.z += a4.z; v.w += a4.w; }
        if (f2) { float4 a4 = *(const float4*)(f2 + n); v.x += a4.x; v.y += a4.y; v.z += a4.z; v.w += a4.w; }
        v.x = fmaxf(v.x, 0.f); v.y = fmaxf(v.y, 0.f);
        v.z = fmaxf(v.z, 0.f); v.w = fmaxf(v.w, 0.f);
        float4 u = *(const float4*)(usw + n);
        acc += v.x*u.x + v.y*u.y + v.z*u.z + v.w*u.w;
    }
#pragma unroll
    for (int o = 16; o; o >>= 1) acc += __shfl_xor_sync(0xffffffffu, acc, o);

    __shared__ float sl[8], sc[8];
    if (lane == 0) {
        float p = acc + usb[0];
        int tchk = (s < Tc) ? 1 : 0;
        float loss = fmaxf(p, 0.f) - (tchk ? p : 0.f) + log1pf(expf(-fabsf(p)));
        float corr = (((p > 0.f) ? 1 : 0) == tchk) ? 1.f : 0.f;
        sl[warp] = loss; sc[warp] = corr;
    }
    __syncthreads();
    if (threadIdx.x == 0) {
        float a = 0.f, c = 0.f;
        for (int w = 0; w < 8; w++) { a += sl[w]; c += sc[w]; }
        g_ppart_loss[blockIdx.x] = a;
        g_ppart_corr[blockIdx.x] = c;
    }
}

// ------------- final deterministic reduction -------------------------------
__global__ void k_finalize(float* __restrict__ out)
{
    __shared__ float sq[256], sqc[256], sp[256], spc[256];
    int t = threadIdx.x;
    float a = 0.f, b = 0.f, c = 0.f, d = 0.f;
    for (int i = t; i < QBLOCKS; i += 256) { a += g_qpart_loss[i]; b += g_qpart_corr[i]; }
    for (int i = t; i < PBLOCKS; i += 256) { c += g_ppart_loss[i]; d += g_ppart_corr[i]; }
    sq[t] = a; sqc[t] = b; sp[t] = c; spc[t] = d;
    __syncthreads();
    for (int o = 128; o; o >>= 1) {
        if (t < o) { sq[t] += sq[t+o]; sqc[t] += sqc[t+o]; sp[t] += sp[t+o]; spc[t] += spc[t+o]; }
        __syncthreads();
    }
    if (t == 0) {
        out[0] = sq[0]  / (float)Bc;   // q_loss
        out[1] = sp[0]  / (float)Bc;   // p_loss
        out[2] = sqc[0] / (float)DB;   // q_acc
        out[3] = spc[0] / (float)SB;   // p_acc
    }
}

// ---------------------------------------------------------------------------
extern "C" void kernel_launch(void* const* d_in, const int* in_sizes, int n_in,
                              void* d_out, int out_size)
{
    const int*   wid      = (const int*)  d_in[0];
    const float* tree_vec = (const float*)d_in[1];
    const float* emb      = (const float*)d_in[2];
    const float* Wz       = (const float*)d_in[3];
    const float* bz       = (const float*)d_in[4];
    const float* Wr       = (const float*)d_in[5];
    const float* Ur       = (const float*)d_in[6];
    const float* br       = (const float*)d_in[7];
    const float* Wh       = (const float*)d_in[8];
    const float* bh       = (const float*)d_in[9];
    const float* W_w      = (const float*)d_in[10];
    const float* W_b      = (const float*)d_in[11];
    const float* U_w      = (const float*)d_in[12];
    const float* U_b      = (const float*)d_in[13];
    const float* Wo_w     = (const float*)d_in[14];
    const float* Wo_b     = (const float*)d_in[15];
    const float* Us_w     = (const float*)d_in[16];
    const float* Us_b     = (const float*)d_in[17];
    float* out = (float*)d_out;

    k_precompute_x<<<dim3(DB/64, Hc/64, 4), 256>>>(wid, emb, Wz, bz, Wh, bh, Wr, br, U_w);
    k_tree<<<dim3(Bc, 2), 256>>>(tree_vec, W_w, W_b, U_w, U_b);

    for (int t = 0; t < Tc; t++) {
        k_scanA<<<dim3(2*Bc/64, Hc/64), 256>>>(t, Wz, Wh);
        if (t < Tc - 1)
            k_scanB<<<dim3(2*Bc/64, Hc/64), 256>>>(t, Ur);
    }

    k_postm<<<dim3(TB/64, Hc/64, 3), 256>>>(W_w, U_w);
    k_logits<<<dim3(DB/64, (Vc + 63)/64), 256>>>(Wo_w, Wo_b);
    k_qreduce<<<QBLOCKS, 256>>>(wid);
    k_p<<<PBLOCKS, 256>>>(Us_w, Us_b);
    k_finalize<<<1, 256>>>(out);
}